// round 14
// baseline (speedup 1.0000x reference)
#include <cuda_runtime.h>
#include <cuda_bf16.h>

// Problem constants (fixed by setup_inputs)
constexpr int B  = 8;
constexpr int N  = 16384;
constexpr int G  = 128;
constexpr int NC = 11;          // N_CLASSES
constexpr float THRESH = 0.3f;  // REG_FG_THRESH
constexpr int BLK  = 128;                       // threads per block == rows per block
constexpr int BLOCKS_PER_BATCH = N / BLK;       // 128
constexpr int F4_ROWS = BLK * 7 / 4;            // 224 float4 per row-region
constexpr int F4_GT   = G * 7 / 4;              // 224 float4 for the gt region

constexpr int   NBUCK   = 16;
constexpr float BUCK_LO  = -50.0f;
constexpr float BUCK_INV = 0.16f;     // 1 / 6.25
constexpr float MARGIN   = 0.125f;

__device__ __forceinline__ int bidx(float v) {
    int k = (int)floorf((v - BUCK_LO) * BUCK_INV);
    return min(max(k, 0), NBUCK - 1);
}

// ---- cp.async helpers ----
__device__ __forceinline__ void cpa16(void* smem, const void* gmem) {
    unsigned saddr = (unsigned)__cvta_generic_to_shared(smem);
    asm volatile("cp.async.ca.shared.global [%0], [%1], 16;"
                 :: "r"(saddr), "l"(gmem));
}
__device__ __forceinline__ void cpa_commit() {
    asm volatile("cp.async.commit_group;");
}
template <int NLeft>
__device__ __forceinline__ void cpa_wait() {
    asm volatile("cp.async.wait_group %0;" :: "n"(NLeft));
}

// Output layout (concatenated, float32):
//   [0,            B*N*7)   batch_rois
//   [B*N*7,        2*B*N*7) gt_of_rois
//   [2*B*N*7,      +B*N)    gt_label_of_rois (as float)
//   [2*B*N*7+B*N,  +B*N)    reg_valid_mask

__global__ __launch_bounds__(BLK)
void ptl_kernel(const float* __restrict__ rois,
                const float* __restrict__ gt,
                const int*   __restrict__ gt_lab,
                const float* __restrict__ assign_gt,
                const int*   __restrict__ assign_lab,
                float* __restrict__ out)
{
    // GT tables
    __shared__ float4 sMin[G];         // bmin.xyz, vol_b
    __shared__ float4 sMax[G];         // bmax.xyz, pad
    __shared__ float  sBox[G][8];      // cx cy cz dx dy dz (-h) label_bits
    // Per-axis bucket masks: sMsk[a][k] = 128-bit mask (uint4) of boxes whose
    // axis-a interval (with margin) intersects bucket k.
    __shared__ uint4  sMsk[3][NBUCK];
    // Staging buffers (row r occupies [r*7, r*7+7); stride 7 coprime to 32
    // -> conflict-free scalar LDS/STS per row)
    __shared__ alignas(16) float sGTin[G * 7];   // gt input (896 floats)
    __shared__ alignas(16) float sGO[BLK * 7];   // gt_of_rois out
    __shared__ alignas(16) float sRO[BLK * 7];   // rois in -> passthrough out
    __shared__ alignas(16) float sAG[BLK * 7];   // assign_gt in

    const int tid   = threadIdx.x;                  // 0..127
    const int batch = blockIdx.x / BLOCKS_PER_BATCH;
    const int rowBase = (blockIdx.x % BLOCKS_PER_BATCH) * BLK;
    const size_t ri = (size_t)batch * N + rowBase + tid;
    const size_t regionBase = ((size_t)batch * N + rowBase) * 7;   // floats
    const size_t gtBase     = (size_t)batch * G * 7;               // floats

    // ---- Async staging: group A = gt region, group B = rois + assign_gt ----
    {
        #pragma unroll
        for (int i = tid; i < F4_GT; i += BLK)
            cpa16(((float4*)sGTin) + i, ((const float4*)(gt + gtBase)) + i);
        cpa_commit();
        #pragma unroll
        for (int i = tid; i < F4_ROWS; i += BLK) {
            cpa16(((float4*)sRO) + i, ((const float4*)(rois      + regionBase)) + i);
            cpa16(((float4*)sAG) + i, ((const float4*)(assign_gt + regionBase)) + i);
        }
        cpa_commit();
    }
    cpa_wait<1>();       // gt region resident (rois/assign_gt may still fly)
    __syncthreads();

    // ---- GT preamble: one box per thread; ballot-built bucket masks ----
    {
        const float* gp = sGTin + tid * 7;
        float cx = gp[0], cy = gp[1], cz = gp[2];
        float dx = gp[3], dy = gp[4], dz = gp[5];
        float h  = gp[6];
        float bmn[3] = { cx - 0.5f * dx, cy - 0.5f * dy, cz - 0.5f * dz };
        float bmx[3] = { cx + 0.5f * dx, cy + 0.5f * dy, cz + 0.5f * dz };
        sMin[tid] = make_float4(bmn[0], bmn[1], bmn[2], dx * dy * dz);
        sMax[tid] = make_float4(bmx[0], bmx[1], bmx[2], 0.f);
        sBox[tid][0] = cx; sBox[tid][1] = cy; sBox[tid][2] = cz;
        sBox[tid][3] = dx; sBox[tid][4] = dy; sBox[tid][5] = dz;
        sBox[tid][6] = -h;  // heading multiplied by -1 per reference
        sBox[tid][7] = __int_as_float(gt_lab[(size_t)batch * G + tid]);

        // Bucket span of this box per axis
        int ka[3], kb[3];
        #pragma unroll
        for (int a = 0; a < 3; ++a) {
            ka[a] = bidx(bmn[a] - MARGIN);
            kb[a] = bidx(bmx[a] + MARGIN);
        }
        // Warp w owns boxes 32w..32w+31; ballot over lanes IS word w of the
        // mask for bucket k. Lane k stores it (k < 16 <= 32). No atomics,
        // no zeroing: every word is written exactly once.
        const int lane = tid & 31;
        const int w    = tid >> 5;
        #pragma unroll
        for (int a = 0; a < 3; ++a) {
            #pragma unroll
            for (int k = 0; k < NBUCK; ++k) {
                const unsigned bal =
                    __ballot_sync(0xffffffffu, (ka[a] <= k) && (k <= kb[a]));
                if (lane == k)
                    ((unsigned*)&sMsk[a][k])[w] = bal;
            }
        }
    }
    cpa_wait<0>();       // rois/assign_gt resident
    __syncthreads();

    // ---- My ROI from staged sRO (conflict-free stride-7 LDS) ----
    const float r0 = sRO[tid * 7 + 0], r1 = sRO[tid * 7 + 1], r2 = sRO[tid * 7 + 2];
    const float r3 = sRO[tid * 7 + 3], r4 = sRO[tid * 7 + 4], r5 = sRO[tid * 7 + 5];

    const float aminx = r0 - 0.5f * r3, amaxx = r0 + 0.5f * r3;
    const float aminy = r1 - 0.5f * r4, amaxy = r1 + 0.5f * r4;
    const float aminz = r2 - 0.5f * r5, amaxz = r2 + 0.5f * r5;
    const float va = r3 * r4 * r5;

    const int alab = assign_lab[ri];    // coalesced 1 int/thread (prefetch early)

    // ---- Candidate mask: OR bucket masks per axis over ROI's bucket span,
    // then AND across axes. A box overlapping the ROI on axis a has its
    // interval intersecting the ROI interval, which lies within buckets
    // k0..k1 -> box present in the ORed mask. Margins dwarf fp rounding,
    // so the mask is conservative; zero-inter boxes can never win the
    // strict-'>' argmax, making the filter exactly lossless.
    unsigned cand[4];
    {
        const float lo[3] = { aminx - MARGIN, aminy - MARGIN, aminz - MARGIN };
        const float hi[3] = { amaxx + MARGIN, amaxy + MARGIN, amaxz + MARGIN };
        #pragma unroll
        for (int a = 0; a < 3; ++a) {
            const int k0 = bidx(lo[a]);
            const int k1 = bidx(hi[a]);
            uint4 m = sMsk[a][k0];
            for (int k = k0 + 1; k <= k1; ++k) {
                const uint4 mm = sMsk[a][k];
                m.x |= mm.x; m.y |= mm.y; m.z |= mm.z; m.w |= mm.w;
            }
            if (a == 0) { cand[0] = m.x; cand[1] = m.y; cand[2] = m.z; cand[3] = m.w; }
            else        { cand[0] &= m.x; cand[1] &= m.y; cand[2] &= m.z; cand[3] &= m.w; }
        }
    }

    // ---- Exact IoU-argmax over candidates (ascending g order) ----
    // iou = inter/(s - inter), s = va + vb, strictly monotone in inter/s
    // => argmax via cross-mult compare; strict '>' keeps first max (jnp.argmax).
    float bi = 0.f, bs = 1.f; int bg = 0;
    #pragma unroll
    for (int c = 0; c < 4; ++c) {
        unsigned m = cand[c];
        while (m) {
            const int b = __ffs(m) - 1;
            m &= m - 1;
            const int g = c * 32 + b;
            const float4 mn = sMin[g];
            const float4 mx = sMax[g];
            float ox = fminf(amaxx, mx.x) - fmaxf(aminx, mn.x);
            float oy = fminf(amaxy, mx.y) - fmaxf(aminy, mn.y);
            float oz = fminf(amaxz, mx.z) - fmaxf(aminz, mn.z);
            ox = fmaxf(ox, 0.0f);
            oy = fmaxf(oy, 0.0f);
            oz = fmaxf(oz, 0.0f);
            const float inter = ox * oy * oz;
            const float s     = va + mn.w;
            if (inter * bs > bi * s) { bi = inter; bs = s; bg = g; }
        }
    }

    // ---- rois passthrough store NOW (sRO stable since sync #2) to overlap
    // these STGs with the epilogue compute below ----
    {
        float4* orr = (float4*)(out + regionBase);
        #pragma unroll
        for (int i = tid; i < F4_ROWS; i += BLK)
            orr[i] = ((const float4*)sRO)[i];
    }

    const bool pos1 = (alab >= 0);
    // max_ov >= THRESH  <=>  bi >= THRESH * clip(s - bi, 1e-6)
    const bool pos2 = (!pos1) && (bi >= THRESH * fmaxf(bs - bi, 1e-6f));

    // ---- label & mask: direct coalesced per-thread stores ----
    {
        float* labBase  = out + (size_t)B * N * 14 + (size_t)batch * N + rowBase;
        float* maskBase = labBase + (size_t)B * N;
        int lab = pos1 ? alab : (pos2 ? __float_as_int(sBox[bg][7]) : NC);
        labBase[tid]  = (float)lab;
        maskBase[tid] = (pos1 || pos2) ? 1.0f : 0.0f;
    }

    // ---- Epilogue into staging (each thread writes only its own row) ----
    #pragma unroll
    for (int k = 0; k < 7; ++k) {
        float gv;
        if (pos1) {
            gv = sAG[tid * 7 + k];
            if (k == 6) gv = -gv;   // assign_gt heading negated per reference
        } else if (pos2) {
            gv = sBox[bg][k];       // heading already negated at store time
        } else {
            gv = 0.0f;              // must write: d_out is poisoned
        }
        sGO[tid * 7 + k] = gv;
    }
    __syncthreads();

    // ---- Cooperative coalesced store of gt_of_rois ----
    {
        float4* ogt = (float4*)(out + (size_t)B * N * 7 + regionBase);
        #pragma unroll
        for (int i = tid; i < F4_ROWS; i += BLK)
            ogt[i] = ((const float4*)sGO)[i];
    }
}

extern "C" void kernel_launch(void* const* d_in, const int* in_sizes, int n_in,
                              void* d_out, int out_size)
{
    const float* rois       = (const float*)d_in[0]; // [B,N,7]
    const float* gt         = (const float*)d_in[1]; // [B,G,7]
    const int*   gt_lab     = (const int*)  d_in[2]; // [B,G]
    const float* assign_gt  = (const float*)d_in[3]; // [B,N,7]
    const int*   assign_lab = (const int*)  d_in[4]; // [B,N]
    float*       out        = (float*)d_out;

    // 128 threads/block, 1 ROI/thread -> 1024 blocks
    ptl_kernel<<<(B * N) / BLK, BLK>>>(rois, gt, gt_lab, assign_gt, assign_lab, out);
}

// round 15
// speedup vs baseline: 1.0292x; 1.0292x over previous
#include <cuda_runtime.h>
#include <cuda_bf16.h>

// Problem constants (fixed by setup_inputs)
constexpr int B  = 8;
constexpr int N  = 16384;
constexpr int G  = 128;
constexpr int NC = 11;          // N_CLASSES
constexpr float THRESH = 0.3f;  // REG_FG_THRESH
constexpr int BLK  = 128;                       // threads per block == rows per block
constexpr int BLOCKS_PER_BATCH = N / BLK;       // 128
constexpr int F4_ROWS = BLK * 7 / 4;            // 224 float4 per row-region
constexpr int F4_GT   = G * 7 / 4;              // 224 float4 for the gt region
constexpr int F4_LAB  = G / 4;                  // 32 float4 for gt_lab

constexpr int   NBUCK   = 16;
constexpr float BUCK_LO  = -50.0f;
constexpr float BUCK_INV = 0.16f;     // 1 / 6.25
constexpr float MARGIN   = 0.125f;

__device__ __forceinline__ int bidx(float v) {
    int k = (int)floorf((v - BUCK_LO) * BUCK_INV);
    return min(max(k, 0), NBUCK - 1);
}

// ---- cp.async helpers ----
__device__ __forceinline__ void cpa16(void* smem, const void* gmem) {
    unsigned saddr = (unsigned)__cvta_generic_to_shared(smem);
    asm volatile("cp.async.ca.shared.global [%0], [%1], 16;"
                 :: "r"(saddr), "l"(gmem));
}
__device__ __forceinline__ void cpa_commit() {
    asm volatile("cp.async.commit_group;");
}
template <int NLeft>
__device__ __forceinline__ void cpa_wait() {
    asm volatile("cp.async.wait_group %0;" :: "n"(NLeft));
}

// Output layout (concatenated, float32):
//   [0,            B*N*7)   batch_rois
//   [B*N*7,        2*B*N*7) gt_of_rois
//   [2*B*N*7,      +B*N)    gt_label_of_rois (as float)
//   [2*B*N*7+B*N,  +B*N)    reg_valid_mask

__global__ __launch_bounds__(BLK)
void ptl_kernel(const float* __restrict__ rois,
                const float* __restrict__ gt,
                const int*   __restrict__ gt_lab,
                const float* __restrict__ assign_gt,
                const int*   __restrict__ assign_lab,
                float* __restrict__ out)
{
    // GT tables
    __shared__ float4 sMin[G];         // bmin.xyz, vol_b
    __shared__ float4 sMax[G];         // bmax.xyz, pad
    __shared__ float  sBox[G][8];      // cx cy cz dx dy dz (-h) label_bits
    // Per-axis bucket masks: sMsk[a][k] = 128-bit mask (uint4) of boxes whose
    // axis-a interval (with margin) intersects bucket k.
    __shared__ uint4  sMsk[3][NBUCK];
    // Staging buffers (row r occupies [r*7, r*7+7); stride 7 coprime to 32
    // -> conflict-free scalar LDS/STS per row)
    __shared__ alignas(16) float sGTin[G * 7];   // gt input (896 floats)
    __shared__ alignas(16) int   sLab[G];        // gt_lab input
    __shared__ alignas(16) float sGO[BLK * 7];   // gt_of_rois out
    __shared__ alignas(16) float sRO[BLK * 7];   // rois in -> passthrough out
    __shared__ alignas(16) float sAG[BLK * 7];   // assign_gt in

    const int tid   = threadIdx.x;                  // 0..127
    const int batch = blockIdx.x / BLOCKS_PER_BATCH;
    const int rowBase = (blockIdx.x % BLOCKS_PER_BATCH) * BLK;
    const size_t ri = (size_t)batch * N + rowBase + tid;
    const size_t regionBase = ((size_t)batch * N + rowBase) * 7;   // floats
    const size_t gtBase     = (size_t)batch * G * 7;               // floats

    // ---- Async staging: group A = gt region + labels, group B = tile ----
    {
        #pragma unroll
        for (int i = tid; i < F4_GT; i += BLK)
            cpa16(((float4*)sGTin) + i, ((const float4*)(gt + gtBase)) + i);
        if (tid < F4_LAB)
            cpa16(((float4*)sLab) + tid,
                  ((const float4*)(gt_lab + (size_t)batch * G)) + tid);
        cpa_commit();
        #pragma unroll
        for (int i = tid; i < F4_ROWS; i += BLK) {
            cpa16(((float4*)sRO) + i, ((const float4*)(rois      + regionBase)) + i);
            cpa16(((float4*)sAG) + i, ((const float4*)(assign_gt + regionBase)) + i);
        }
        cpa_commit();

        // zero bucket masks while copies are in flight
        unsigned* mw = (unsigned*)sMsk;          // 3*16*4 = 192 words
        #pragma unroll
        for (int i = tid; i < 192; i += BLK) mw[i] = 0u;
    }
    cpa_wait<1>();       // gt region + labels resident (tile may still fly)
    __syncthreads();

    // ---- GT preamble: one box per thread ----
    {
        const float* gp = sGTin + tid * 7;
        float cx = gp[0], cy = gp[1], cz = gp[2];
        float dx = gp[3], dy = gp[4], dz = gp[5];
        float h  = gp[6];
        float bmn[3] = { cx - 0.5f * dx, cy - 0.5f * dy, cz - 0.5f * dz };
        float bmx[3] = { cx + 0.5f * dx, cy + 0.5f * dy, cz + 0.5f * dz };
        sMin[tid] = make_float4(bmn[0], bmn[1], bmn[2], dx * dy * dz);
        sMax[tid] = make_float4(bmx[0], bmx[1], bmx[2], 0.f);
        sBox[tid][0] = cx; sBox[tid][1] = cy; sBox[tid][2] = cz;
        sBox[tid][3] = dx; sBox[tid][4] = dy; sBox[tid][5] = dz;
        sBox[tid][6] = -h;  // heading multiplied by -1 per reference
        sBox[tid][7] = __int_as_float(sLab[tid]);

        const unsigned bit = 1u << (tid & 31);
        const int w = tid >> 5;
        #pragma unroll
        for (int a = 0; a < 3; ++a) {
            const int ka = bidx(bmn[a] - MARGIN);
            const int kb = bidx(bmx[a] + MARGIN);
            for (int k = ka; k <= kb; ++k)
                atomicOr(((unsigned*)&sMsk[a][k]) + w, bit);
        }
    }
    cpa_wait<0>();       // rois/assign_gt resident
    __syncthreads();

    // ---- My ROI from staged sRO (conflict-free stride-7 LDS) ----
    const float r0 = sRO[tid * 7 + 0], r1 = sRO[tid * 7 + 1], r2 = sRO[tid * 7 + 2];
    const float r3 = sRO[tid * 7 + 3], r4 = sRO[tid * 7 + 4], r5 = sRO[tid * 7 + 5];

    const float aminx = r0 - 0.5f * r3, amaxx = r0 + 0.5f * r3;
    const float aminy = r1 - 0.5f * r4, amaxy = r1 + 0.5f * r4;
    const float aminz = r2 - 0.5f * r5, amaxz = r2 + 0.5f * r5;
    const float va = r3 * r4 * r5;

    const int alab = assign_lab[ri];    // coalesced 1 int/thread (prefetch early)

    // ---- Candidate mask: OR bucket masks per axis over ROI's bucket span,
    // then AND across axes. A box overlapping the ROI on axis a has its
    // interval intersecting the ROI interval, which lies within buckets
    // k0..k1 -> box present in the ORed mask. Margins dwarf fp rounding,
    // so the mask is conservative; zero-inter boxes can never win the
    // strict-'>' argmax, making the filter exactly lossless.
    unsigned cand[4];
    {
        const float lo[3] = { aminx - MARGIN, aminy - MARGIN, aminz - MARGIN };
        const float hi[3] = { amaxx + MARGIN, amaxy + MARGIN, amaxz + MARGIN };
        #pragma unroll
        for (int a = 0; a < 3; ++a) {
            const int k0 = bidx(lo[a]);
            const int k1 = bidx(hi[a]);
            uint4 m = sMsk[a][k0];
            for (int k = k0 + 1; k <= k1; ++k) {
                const uint4 mm = sMsk[a][k];
                m.x |= mm.x; m.y |= mm.y; m.z |= mm.z; m.w |= mm.w;
            }
            if (a == 0) { cand[0] = m.x; cand[1] = m.y; cand[2] = m.z; cand[3] = m.w; }
            else        { cand[0] &= m.x; cand[1] &= m.y; cand[2] &= m.z; cand[3] &= m.w; }
        }
    }

    // ---- Exact IoU-argmax over candidates (ascending g order) ----
    // iou = inter/(s - inter), s = va + vb, strictly monotone in inter/s
    // => argmax via cross-mult compare; strict '>' keeps first max (jnp.argmax).
    float bi = 0.f, bs = 1.f; int bg = 0;
    #pragma unroll
    for (int c = 0; c < 4; ++c) {
        unsigned m = cand[c];
        while (m) {
            const int b = __ffs(m) - 1;
            m &= m - 1;
            const int g = c * 32 + b;
            const float4 mn = sMin[g];
            const float4 mx = sMax[g];
            float ox = fminf(amaxx, mx.x) - fmaxf(aminx, mn.x);
            float oy = fminf(amaxy, mx.y) - fmaxf(aminy, mn.y);
            float oz = fminf(amaxz, mx.z) - fmaxf(aminz, mn.z);
            ox = fmaxf(ox, 0.0f);
            oy = fmaxf(oy, 0.0f);
            oz = fmaxf(oz, 0.0f);
            const float inter = ox * oy * oz;
            const float s     = va + mn.w;
            if (inter * bs > bi * s) { bi = inter; bs = s; bg = g; }
        }
    }

    // ---- rois passthrough store NOW (sRO stable since sync #2) to overlap
    // these STGs with the epilogue compute below ----
    {
        float4* orr = (float4*)(out + regionBase);
        #pragma unroll
        for (int i = tid; i < F4_ROWS; i += BLK)
            orr[i] = ((const float4*)sRO)[i];
    }

    const bool pos1 = (alab >= 0);
    // max_ov >= THRESH  <=>  bi >= THRESH * clip(s - bi, 1e-6)
    const bool pos2 = (!pos1) && (bi >= THRESH * fmaxf(bs - bi, 1e-6f));

    // ---- label & mask: direct coalesced per-thread stores ----
    {
        float* labBase  = out + (size_t)B * N * 14 + (size_t)batch * N + rowBase;
        float* maskBase = labBase + (size_t)B * N;
        int lab = pos1 ? alab : (pos2 ? __float_as_int(sBox[bg][7]) : NC);
        labBase[tid]  = (float)lab;
        maskBase[tid] = (pos1 || pos2) ? 1.0f : 0.0f;
    }

    // ---- Epilogue: warp-local staging + warp-local coalesced store.
    // Warp w's 32 rows occupy exactly float4 range [w*56, (w+1)*56) of the
    // gt_of_rois region, so only __syncwarp() is needed - no block barrier.
    #pragma unroll
    for (int k = 0; k < 7; ++k) {
        float gv;
        if (pos1) {
            gv = sAG[tid * 7 + k];
            if (k == 6) gv = -gv;   // assign_gt heading negated per reference
        } else if (pos2) {
            gv = sBox[bg][k];       // heading already negated at store time
        } else {
            gv = 0.0f;              // must write: d_out is poisoned
        }
        sGO[tid * 7 + k] = gv;
    }
    __syncwarp();
    {
        const int w    = tid >> 5;
        const int lane = tid & 31;
        float4* ogt = (float4*)(out + (size_t)B * N * 7 + regionBase);
        #pragma unroll
        for (int i = w * 56 + lane; i < (w + 1) * 56; i += 32)
            ogt[i] = ((const float4*)sGO)[i];
    }
}

extern "C" void kernel_launch(void* const* d_in, const int* in_sizes, int n_in,
                              void* d_out, int out_size)
{
    const float* rois       = (const float*)d_in[0]; // [B,N,7]
    const float* gt         = (const float*)d_in[1]; // [B,G,7]
    const int*   gt_lab     = (const int*)  d_in[2]; // [B,G]
    const float* assign_gt  = (const float*)d_in[3]; // [B,N,7]
    const int*   assign_lab = (const int*)  d_in[4]; // [B,N]
    float*       out        = (float*)d_out;

    // 128 threads/block, 1 ROI/thread -> 1024 blocks
    ptl_kernel<<<(B * N) / BLK, BLK>>>(rois, gt, gt_lab, assign_gt, assign_lab, out);
}